// round 11
// baseline (speedup 1.0000x reference)
#include <cuda_runtime.h>
#include <cuda_bf16.h>
#include <cstdint>

#define NHN 50000
#define NGN 50000
#define NE  1600000
#define NGR 16
#define SCAN_BLKS 256
#define CH 196   // SCAN_BLKS * CH >= NGN

// ---------------- scratch (device globals; no allocations) ----------------
__device__ __align__(16) float g_H1[(size_t)NHN * 128];   // x_h@W1aL^T + b1a
__device__ __align__(16) float g_S [(size_t)NGN * 128];   // sum of leaky(z_e) per target
__device__ __align__(16) float g_T2[(size_t)NGN * 128];   // leaky(node-MLP stage1)
__device__ __align__(16) float g_WtH1[64 * 128];          // W1a[:, :64]^T
__device__ __align__(16) __nv_bfloat16 g_WtEh[64 * 128];  // bf16 hi of W1a[:, 64:]^T
__device__ __align__(16) __nv_bfloat16 g_WtEl[64 * 128];  // bf16 lo residual
__device__ __align__(16) float g_WtN1[256 * 128];
__device__ __align__(16) float g_WtN2[128 * 128];
__device__ __align__(16) float g_cvec[128];
__device__ __align__(16) float g_UW[NGR * 128];
// counting-sort scratch
__device__ int g_cnt[NGN];        // per-target degree (histogram) — also deg for MODE2
__device__ int g_base[NGN];
__device__ int g_cur[NGN];
__device__ int g_bsum[SCAN_BLKS];
__device__ int g_boff[SCAN_BLKS];
__device__ int g_perm[NE];        // sorted-order -> original edge id
__device__ int g_srcs[NE];        // src of sorted edge
__device__ int g_tgts[NE];        // tgt of sorted edge
__device__ int g_is64_e;
__device__ int g_is64_b;

// ---------------- packed f32x2 helpers (scalar GEMMs) ----------------
__device__ __forceinline__ unsigned long long pack2(float x) {
    unsigned long long r;
    asm("mov.b64 %0, {%1, %1};" : "=l"(r) : "f"(x));
    return r;
}
__device__ __forceinline__ void ffma2(unsigned long long& c, unsigned long long a,
                                      unsigned long long b) {
    asm("fma.rn.f32x2 %0, %1, %2, %0;" : "+l"(c) : "l"(a), "l"(b));
}
__device__ __forceinline__ float2 unpack2(unsigned long long v) {
    float2 f;
    asm("mov.b64 {%0, %1}, %2;" : "=f"(f.x), "=f"(f.y) : "l"(v));
    return f;
}

// ---------------- mma helpers ----------------
__device__ __forceinline__ uint32_t s2u(const void* p) {
    return (uint32_t)__cvta_generic_to_shared(p);
}
__device__ __forceinline__ void ldm4(uint32_t* r, uint32_t addr) {
    asm volatile("ldmatrix.sync.aligned.m8n8.x4.shared.b16 {%0,%1,%2,%3}, [%4];"
                 : "=r"(r[0]), "=r"(r[1]), "=r"(r[2]), "=r"(r[3]) : "r"(addr));
}
__device__ __forceinline__ void ldm4t(uint32_t* r, uint32_t addr) {
    asm volatile("ldmatrix.sync.aligned.m8n8.x4.trans.shared.b16 {%0,%1,%2,%3}, [%4];"
                 : "=r"(r[0]), "=r"(r[1]), "=r"(r[2]), "=r"(r[3]) : "r"(addr));
}
__device__ __forceinline__ void mma16816(float* d, const uint32_t* a, uint32_t b0, uint32_t b1) {
    asm volatile("mma.sync.aligned.m16n8k16.row.col.f32.bf16.bf16.f32 "
                 "{%0,%1,%2,%3}, {%4,%5,%6,%7}, {%8,%9}, {%0,%1,%2,%3};"
                 : "+f"(d[0]), "+f"(d[1]), "+f"(d[2]), "+f"(d[3])
                 : "r"(a[0]), "r"(a[1]), "r"(a[2]), "r"(a[3]), "r"(b0), "r"(b1));
}
__device__ __forceinline__ uint32_t cvt2bf(float lo, float hi) {
    uint32_t r;
    asm("cvt.rn.bf16x2.f32 %0, %1, %2;" : "=r"(r) : "f"(hi), "f"(lo));
    return r;
}

// ---------------- zero scratch + dtype detection (merged) ----------------
__global__ void k_zerodetect(const void* eidx, const void* batch) {
    if (blockIdx.x == 0 && threadIdx.x == 0) {
        const unsigned* p = (const unsigned*)eidx;
        int is64 = 1;
        for (int i = 0; i < 32; i++) {
            unsigned lo = p[2 * i], hi = p[2 * i + 1];
            if (hi != 0u || lo >= (unsigned)NHN) { is64 = 0; break; }
        }
        g_is64_e = is64;
        const unsigned* q = (const unsigned*)batch;
        int b64 = 1;
        for (int i = 0; i < 32; i++) {
            unsigned lo = q[2 * i], hi = q[2 * i + 1];
            if (hi != 0u || lo >= (unsigned)NGR) { b64 = 0; break; }
        }
        g_is64_b = b64;
    }
    long long n4 = (long long)NGN * 128 / 4;
    long long stride = (long long)gridDim.x * blockDim.x;
    for (long long i = (long long)blockIdx.x * blockDim.x + threadIdx.x; i < n4; i += stride)
        ((float4*)g_S)[i] = make_float4(0.f, 0.f, 0.f, 0.f);
    for (long long i = (long long)blockIdx.x * blockDim.x + threadIdx.x; i < NGN; i += stride)
        g_cnt[i] = 0;
}

// ---------------- counting sort by target ----------------
__global__ void k_hist(const void* eidx) {
    long long e = (long long)blockIdx.x * blockDim.x + threadIdx.x;
    if (e >= NE) return;
    int t;
    if (g_is64_e) t = (int)((const long long*)eidx)[(long long)NE + e];
    else          t = ((const int*)eidx)[(long long)NE + e];
    atomicAdd(&g_cnt[t], 1);
}

__global__ void k_scan1() {   // per-chunk sums
    __shared__ int sm[256];
    int b = blockIdx.x, t = threadIdx.x;
    int idx = b * CH + t;
    sm[t] = (t < CH && idx < NGN) ? g_cnt[idx] : 0;
    __syncthreads();
    for (int off = 128; off > 0; off >>= 1) {
        if (t < off) sm[t] += sm[t + off];
        __syncthreads();
    }
    if (t == 0) g_bsum[b] = sm[0];
}

__global__ void k_scan2() {   // exclusive scan of chunk sums (single block)
    __shared__ int sm[SCAN_BLKS];
    int t = threadIdx.x;
    sm[t] = g_bsum[t];
    __syncthreads();
    if (t == 0) {
        int run = 0;
        for (int i = 0; i < SCAN_BLKS; i++) { int v = sm[i]; sm[i] = run; run += v; }
    }
    __syncthreads();
    g_boff[t] = sm[t];
}

__global__ void k_scan3() {   // in-chunk exclusive scan + cursor init
    __shared__ int sm[CH];
    int b = blockIdx.x, t = threadIdx.x;
    int idx = b * CH + t;
    if (t < CH) sm[t] = (idx < NGN) ? g_cnt[idx] : 0;
    __syncthreads();
    if (t == 0) {
        int run = g_boff[b];
        for (int i = 0; i < CH; i++) { int v = sm[i]; sm[i] = run; run += v; }
    }
    __syncthreads();
    if (t < CH && idx < NGN) {
        g_base[idx] = sm[t];
        g_cur[idx]  = sm[t];
    }
}

__global__ void k_place(const void* eidx) {
    long long e = (long long)blockIdx.x * blockDim.x + threadIdx.x;
    if (e >= NE) return;
    int s, t;
    if (g_is64_e) {
        s = (int)((const long long*)eidx)[e];
        t = (int)((const long long*)eidx)[(long long)NE + e];
    } else {
        s = ((const int*)eidx)[e];
        t = ((const int*)eidx)[(long long)NE + e];
    }
    int pos = atomicAdd(&g_cur[t], 1);
    g_perm[pos] = (int)e;
    g_srcs[pos] = s;
    g_tgts[pos] = t;
}

// ---------------- weight precompute / transposes ----------------
__global__ void k_prep(const float* __restrict__ W1a, const float* __restrict__ W1b,
                       const float* __restrict__ W2a, const float* __restrict__ W2b,
                       const float* __restrict__ b1b, const float* __restrict__ u) {
    int b = blockIdx.x, t = threadIdx.x;
    if (b < 128) {
        __shared__ float wrow[128];
        wrow[t] = W2a[b * 320 + 128 + t];
        __syncthreads();
        float s = 0.f;
        for (int p = 0; p < 128; p++) s += wrow[p] * W1b[p * 128 + t];
        g_WtN1[(128 + t) * 128 + b] = s;
        if (t == 0) {
            float c = 0.f;
            for (int p = 0; p < 128; p++) c += wrow[p] * b1b[p];
            g_cvec[b] = c;
        }
    } else if (b == 128) {
        for (int i = t; i < 64 * 128; i += 128) {
            int k = i >> 7, j = i & 127;
            g_WtH1[i] = W1a[j * 128 + k];
            float w = W1a[j * 128 + 64 + k];
            __nv_bfloat16 h = __float2bfloat16(w);
            g_WtEh[i] = h;
            g_WtEl[i] = __float2bfloat16(w - __bfloat162float(h));
        }
    } else if (b == 129) {
        for (int i = t; i < 128 * 128; i += 128) {
            int k = i >> 7, j = i & 127;
            g_WtN1[i] = W2a[j * 320 + k];
        }
    } else if (b == 130) {
        for (int i = t; i < 128 * 128; i += 128) {
            int k = i >> 7, j = i & 127;
            g_WtN2[i] = W2b[j * 128 + k];
        }
    } else {
        for (int i = t; i < NGR * 128; i += 128) {
            int g = i >> 7, j = i & 127;
            float s = 0.f;
            for (int k = 0; k < 64; k++) s += u[g * 64 + k] * W2a[j * 320 + 256 + k];
            g_UW[i] = s;
        }
    }
}

// ================= tensor-core edge kernel (sorted edges, segmented epilogue) =================
#define AE_STR 72     // bf16 per A row (64 + 8 pad)
#define BE_STR 136    // bf16 per B row (128 + 8 pad)
#define SME_AL 18432
#define SME_BH 36864
#define SME_BL 54272
#define SME_TOT 72192   // + 128 ints for perm staging

__device__ __forceinline__ void split_store(__nv_bfloat16* Ah, __nv_bfloat16* Al,
                                            int off, float4 v) {
    uint32_t ph01 = cvt2bf(v.x, v.y);
    uint32_t ph23 = cvt2bf(v.z, v.w);
    float l0 = v.x - __uint_as_float(ph01 << 16);
    float l1 = v.y - __uint_as_float(ph01 & 0xffff0000u);
    float l2 = v.z - __uint_as_float(ph23 << 16);
    float l3 = v.w - __uint_as_float(ph23 & 0xffff0000u);
    uint32_t pl01 = cvt2bf(l0, l1);
    uint32_t pl23 = cvt2bf(l2, l3);
    *(uint2*)(Ah + off) = make_uint2(ph01, ph23);
    *(uint2*)(Al + off) = make_uint2(pl01, pl23);
}

extern __shared__ __align__(16) char smdyn[];

__launch_bounds__(256, 2)
__global__ void k_edge(const float* __restrict__ EA) {
    __nv_bfloat16* Ah = (__nv_bfloat16*)smdyn;
    __nv_bfloat16* Al = (__nv_bfloat16*)(smdyn + SME_AL);
    __nv_bfloat16* Bh = (__nv_bfloat16*)(smdyn + SME_BH);
    __nv_bfloat16* Bl = (__nv_bfloat16*)(smdyn + SME_BL);
    int* pe_s = (int*)(smdyn + SME_BL + 17408);   // after Bl (64*136*2=17408)
    float* Cs = (float*)smdyn;

    const int tid = threadIdx.x;
    const int lane = tid & 31, wid = tid >> 5;
    const int wm = (wid & 3) * 16;       // warp M offset within 64-row half
    const int wn = (wid >> 2) * 64;
    const long long m0 = (long long)blockIdx.x * 128;

    // stage perm for this block's 128 sorted edges
    if (tid < 128) pe_s[tid] = g_perm[m0 + tid];

    float d[2][8][4];
#pragma unroll
    for (int mf = 0; mf < 2; mf++)
#pragma unroll
        for (int nf = 0; nf < 8; nf++)
#pragma unroll
            for (int e = 0; e < 4; e++) d[mf][nf][e] = 0.f;

    const uint32_t uAh = s2u(Ah), uAl = s2u(Al), uBh = s2u(Bh), uBl = s2u(Bl);

    // ---- stage entire B: 64 rows x 128 cols hi+lo (independent of perm) ----
#pragma unroll
    for (int it = 0; it < 8; it++) {
        int q = tid + it * 256;
        int row = q >> 5, c = q & 31;
        int off = row * BE_STR + c * 4;
        *(uint2*)(Bh + off) = *(const uint2*)(g_WtEh + row * 128 + c * 4);
        *(uint2*)(Bl + off) = *(const uint2*)(g_WtEl + row * 128 + c * 4);
    }
    __syncthreads();   // pe_s ready

    // ---- stage entire A via perm gather: 128 rows x 64 floats ----
#pragma unroll
    for (int it = 0; it < 8; it++) {
        int q = tid + it * 256;
        int m = q >> 4, k4 = q & 15;
        long long row = pe_s[m];
        float4 v = ((const float4*)(EA + row * 64))[k4];
        split_store(Ah, Al, m * AE_STR + k4 * 4, v);
    }
    __syncthreads();

    // ---- 4 x k16 mma chunks; warp tile rows = wm + mf*64 ----
#pragma unroll
    for (int kc = 0; kc < 4; kc++) {
        uint32_t ah[2][4], al[2][4];
#pragma unroll
        for (int mf = 0; mf < 2; mf++) {
            uint32_t aoff = (uint32_t)(((wm + mf * 64 + (lane & 15)) * AE_STR +
                                        kc * 16 + ((lane >> 4) << 3)) * 2);
            ldm4(ah[mf], uAh + aoff);
            ldm4(al[mf], uAl + aoff);
        }
#pragma unroll
        for (int nf2 = 0; nf2 < 4; nf2++) {
            uint32_t boff = (uint32_t)(((kc * 16 + (lane & 15)) * BE_STR +
                                        wn + nf2 * 16 + ((lane >> 4) << 3)) * 2);
            uint32_t bh[4], bl[4];
            ldm4t(bh, uBh + boff);
            ldm4t(bl, uBl + boff);
#pragma unroll
            for (int mf = 0; mf < 2; mf++) {
#pragma unroll
                for (int tt = 0; tt < 2; tt++) {
                    float* dd = d[mf][nf2 * 2 + tt];
                    mma16816(dd, ah[mf], bh[2 * tt], bh[2 * tt + 1]);
                    mma16816(dd, ah[mf], bl[2 * tt], bl[2 * tt + 1]);
                    mma16816(dd, al[mf], bh[2 * tt], bh[2 * tt + 1]);
                }
            }
        }
    }
    __syncthreads();

    // ---- epilogue: pass p holds sorted rows [m0+p*64, m0+p*64+64) contiguously ----
    // warp handles 8 consecutive sorted rows; lane covers 4 cols at lane*4.
    const int c0 = lane * 4;
#pragma unroll
    for (int p = 0; p < 2; p++) {
        int rowc = (wid & 3) * 16 + (lane >> 2);
        int colc = wn + 2 * (lane & 3);
#pragma unroll
        for (int nf = 0; nf < 8; nf++) {
            *(float2*)&Cs[rowc * 128 + colc + nf * 8] = make_float2(d[p][nf][0], d[p][nf][1]);
            *(float2*)&Cs[(rowc + 8) * 128 + colc + nf * 8] = make_float2(d[p][nf][2], d[p][nf][3]);
        }
        __syncthreads();

        long long base = m0 + p * 64 + wid * 8;
        int tprev = g_tgts[base];
        float r0 = 0.f, r1 = 0.f, r2 = 0.f, r3 = 0.f;
#pragma unroll
        for (int r = 0; r < 8; r++) {
            int t = g_tgts[base + r];
            if (t != tprev) {
                float* dst = g_S + (long long)tprev * 128 + c0;
                asm volatile("red.global.add.v4.f32 [%0], {%1,%2,%3,%4};"
                             :: "l"(dst), "f"(r0), "f"(r1), "f"(r2), "f"(r3) : "memory");
                r0 = r1 = r2 = r3 = 0.f;
                tprev = t;
            }
            long long s = g_srcs[base + r];
            float4 h = *(const float4*)(g_H1 + s * 128 + c0);
            const float* cr = Cs + (wid * 8 + r) * 128 + c0;
            float v0 = cr[0] + h.x, v1 = cr[1] + h.y, v2 = cr[2] + h.z, v3 = cr[3] + h.w;
            v0 = (v0 >= 0.f) ? v0 : 0.1f * v0;
            v1 = (v1 >= 0.f) ? v1 : 0.1f * v1;
            v2 = (v2 >= 0.f) ? v2 : 0.1f * v2;
            v3 = (v3 >= 0.f) ? v3 : 0.1f * v3;
            r0 += v0; r1 += v1; r2 += v2; r3 += v3;
        }
        float* dst = g_S + (long long)tprev * 128 + c0;
        asm volatile("red.global.add.v4.f32 [%0], {%1,%2,%3,%4};"
                     :: "l"(dst), "f"(r0), "f"(r1), "f"(r2), "f"(r3) : "memory");
        __syncthreads();
    }
}

// ---------------- scalar register-tiled GEMM (modes 0/2/3) ----------------
template <int KTOT, int MODE>
__launch_bounds__(256)
__global__ void k_gemm(const float* __restrict__ A0, const float* __restrict__ bias,
                       float* __restrict__ Cout, int Mrows, const void* __restrict__ idx) {
    __shared__ float As[128 * 32];
    __shared__ float Bs[32 * 128];

    const int tid = threadIdx.x;
    const int tx = tid & 15, ty = tid >> 4;
    const int r0 = ty * 8, c0 = tx * 8;
    const int m0 = blockIdx.x * 128;

    const float* Bt = (MODE == 0) ? g_WtH1 : (MODE == 2) ? g_WtN1 : g_WtN2;

    unsigned long long acc2[8][4];
#pragma unroll
    for (int i = 0; i < 8; i++)
#pragma unroll
        for (int j = 0; j < 4; j++) acc2[i][j] = 0ull;

    for (int ks = 0; ks < KTOT; ks += 32) {
        const float* Asrc;
        int koff, lda;
        if (MODE == 2) {
            lda = 128;
            if (ks < 128) { Asrc = A0;  koff = ks; }
            else          { Asrc = g_S; koff = ks - 128; }
        } else if (MODE == 3) {
            Asrc = g_T2; lda = 128; koff = ks;
        } else {
            Asrc = A0; lda = KTOT; koff = ks;
        }
#pragma unroll
        for (int it = 0; it < 4; it++) {
            int q = tid + it * 256;
            int m = q >> 3, k4 = q & 7;
            float4 v = make_float4(0.f, 0.f, 0.f, 0.f);
            if (m0 + m < Mrows)
                v = ((const float4*)(Asrc + (long long)(m0 + m) * lda + koff))[k4];
            ((float4*)As)[q] = v;
        }
#pragma unroll
        for (int it = 0; it < 4; it++) {
            int q = tid + it * 256;
            ((float4*)Bs)[q] = ((const float4*)Bt)[(long long)(ks * 32) + q];
        }
        __syncthreads();

#pragma unroll
        for (int kk4 = 0; kk4 < 8; kk4++) {
            float4 av[8];
#pragma unroll
            for (int i = 0; i < 8; i++) av[i] = ((const float4*)As)[(r0 + i) * 8 + kk4];
#pragma unroll
            for (int u = 0; u < 4; u++) {
                const ulonglong2* bp = (const ulonglong2*)(Bs + (kk4 * 4 + u) * 128 + c0);
                ulonglong2 b0 = bp[0];
                ulonglong2 b1 = bp[1];
#pragma unroll
                for (int i = 0; i < 8; i++) {
                    float a = (u == 0) ? av[i].x : (u == 1) ? av[i].y
                             : (u == 2) ? av[i].z : av[i].w;
                    unsigned long long a2 = pack2(a);
                    ffma2(acc2[i][0], a2, b0.x);
                    ffma2(acc2[i][1], a2, b0.y);
                    ffma2(acc2[i][2], a2, b1.x);
                    ffma2(acc2[i][3], a2, b1.y);
                }
            }
        }
        __syncthreads();
    }

    float acc[8][8];
#pragma unroll
    for (int i = 0; i < 8; i++)
#pragma unroll
        for (int j = 0; j < 4; j++) {
            float2 f = unpack2(acc2[i][j]);
            acc[i][2 * j]     = f.x;
            acc[i][2 * j + 1] = f.y;
        }

    if (MODE == 0 || MODE == 3) {
        float bloc[8];
#pragma unroll
        for (int j = 0; j < 8; j++) bloc[j] = bias[c0 + j];
        float* C = (MODE == 0) ? g_H1 : Cout;
#pragma unroll
        for (int i = 0; i < 8; i++) {
            int m = m0 + r0 + i;
            if (m < Mrows) {
                float4* dst = (float4*)(C + (long long)m * 128 + c0);
                dst[0] = make_float4(acc[i][0] + bloc[0], acc[i][1] + bloc[1],
                                     acc[i][2] + bloc[2], acc[i][3] + bloc[3]);
                dst[1] = make_float4(acc[i][4] + bloc[4], acc[i][5] + bloc[5],
                                     acc[i][6] + bloc[6], acc[i][7] + bloc[7]);
            }
        }
    }
    if (MODE == 2) {
        const int is64 = g_is64_b;
        float bloc[8], cloc[8];
#pragma unroll
        for (int j = 0; j < 8; j++) { bloc[j] = bias[c0 + j]; cloc[j] = g_cvec[c0 + j]; }
#pragma unroll
        for (int i = 0; i < 8; i++) {
            int m = m0 + r0 + i;
            if (m < Mrows) {
                long long g = is64 ? ((const long long*)idx)[m] : (long long)((const int*)idx)[m];
                float dg = (float)g_cnt[m];   // degree from histogram
                const float* uw = g_UW + g * 128 + c0;
                float v[8];
#pragma unroll
                for (int j = 0; j < 8; j++) {
                    float z = acc[i][j] + bloc[j] + dg * cloc[j] + uw[j];
                    v[j] = (z >= 0.f) ? z : 0.1f * z;
                }
                float4* dst = (float4*)(g_T2 + (long long)m * 128 + c0);
                dst[0] = make_float4(v[0], v[1], v[2], v[3]);
                dst[1] = make_float4(v[4], v[5], v[6], v[7]);
            }
        }
    }
}

// ---------------- launch ----------------
extern "C" void kernel_launch(void* const* d_in, const int* in_sizes, int n_in,
                              void* d_out, int out_size) {
    const float* x_h       = (const float*)d_in[0];
    const float* x_g       = (const float*)d_in[1];
    const float* edge_attr = (const float*)d_in[2];
    const float* u         = (const float*)d_in[3];
    const float* W1a       = (const float*)d_in[4];
    const float* b1a       = (const float*)d_in[5];
    const float* W1b       = (const float*)d_in[6];
    const float* b1b       = (const float*)d_in[7];
    const float* W2a       = (const float*)d_in[8];
    const float* b2a       = (const float*)d_in[9];
    const float* W2b       = (const float*)d_in[10];
    const float* b2b       = (const float*)d_in[11];
    const void*  eidx      = d_in[12];
    const void*  batch     = d_in[13];
    float* out = (float*)d_out;

    cudaFuncSetAttribute(k_edge, cudaFuncAttributeMaxDynamicSharedMemorySize, SME_TOT);

    const int gb_nodes = (NGN + 127) / 128;   // 391
    const int gb_edges = NE / 128;            // 12500

    k_zerodetect<<<512, 256>>>(eidx, batch);                    // 0: zero g_S/g_cnt + dtype flags
    k_hist<<<(NE + 255) / 256, 256>>>(eidx);                    // 1
    k_prep<<<132, 128>>>(W1a, W1b, W2a, W2b, b1b, u);          // 2
    k_scan1<<<SCAN_BLKS, 256>>>();                              // 3
    k_scan2<<<1, SCAN_BLKS>>>();                                // 4
    k_scan3<<<SCAN_BLKS, 256>>>();                              // 5
    k_place<<<(NE + 255) / 256, 256>>>(eidx);                   // 6
    k_gemm<64, 0><<<gb_nodes, 256>>>(x_h, b1a, nullptr, NHN, nullptr);   // 7
    k_edge<<<gb_edges, 256, SME_TOT>>>(edge_attr);              // 8
    k_gemm<256, 2><<<gb_nodes, 256>>>(x_g, b2a, nullptr, NGN, batch);    // 9
    k_gemm<128, 3><<<gb_nodes, 256>>>(nullptr, b2b, out, NGN, nullptr);  // 10
}

// round 12
// speedup vs baseline: 1.0790x; 1.0790x over previous
#include <cuda_runtime.h>
#include <cuda_bf16.h>
#include <cstdint>

#define NHN 50000
#define NGN 50000
#define NE  1600000
#define NGR 16

// ---------------- scratch (device globals; no allocations) ----------------
__device__ __align__(16) float g_S [(size_t)NGN * 128];   // sum of leaky(z_e) per target
__device__ __align__(16) float g_T2[(size_t)NGN * 128];   // leaky(node-MLP stage1)
__device__ __align__(16) __nv_bfloat16 g_WtFh[128 * 128]; // bf16 hi of full W1a^T [k][j]
__device__ __align__(16) __nv_bfloat16 g_WtFl[128 * 128]; // bf16 lo residual
__device__ __align__(16) float g_WtN1[256 * 128];
__device__ __align__(16) float g_WtN2[128 * 128];
__device__ __align__(16) float g_cvec[128];
__device__ __align__(16) float g_UW[NGR * 128];
__device__ int g_deg[NGN];
__device__ int g_is64_e;
__device__ int g_is64_b;

// ---------------- packed f32x2 helpers (scalar GEMMs) ----------------
__device__ __forceinline__ unsigned long long pack2(float x) {
    unsigned long long r;
    asm("mov.b64 %0, {%1, %1};" : "=l"(r) : "f"(x));
    return r;
}
__device__ __forceinline__ void ffma2(unsigned long long& c, unsigned long long a,
                                      unsigned long long b) {
    asm("fma.rn.f32x2 %0, %1, %2, %0;" : "+l"(c) : "l"(a), "l"(b));
}
__device__ __forceinline__ float2 unpack2(unsigned long long v) {
    float2 f;
    asm("mov.b64 {%0, %1}, %2;" : "=f"(f.x), "=f"(f.y) : "l"(v));
    return f;
}

// ---------------- mma helpers ----------------
__device__ __forceinline__ uint32_t s2u(const void* p) {
    return (uint32_t)__cvta_generic_to_shared(p);
}
__device__ __forceinline__ void ldm4(uint32_t* r, uint32_t addr) {
    asm volatile("ldmatrix.sync.aligned.m8n8.x4.shared.b16 {%0,%1,%2,%3}, [%4];"
                 : "=r"(r[0]), "=r"(r[1]), "=r"(r[2]), "=r"(r[3]) : "r"(addr));
}
__device__ __forceinline__ void ldm4t(uint32_t* r, uint32_t addr) {
    asm volatile("ldmatrix.sync.aligned.m8n8.x4.trans.shared.b16 {%0,%1,%2,%3}, [%4];"
                 : "=r"(r[0]), "=r"(r[1]), "=r"(r[2]), "=r"(r[3]) : "r"(addr));
}
__device__ __forceinline__ void mma16816(float* d, const uint32_t* a, uint32_t b0, uint32_t b1) {
    asm volatile("mma.sync.aligned.m16n8k16.row.col.f32.bf16.bf16.f32 "
                 "{%0,%1,%2,%3}, {%4,%5,%6,%7}, {%8,%9}, {%0,%1,%2,%3};"
                 : "+f"(d[0]), "+f"(d[1]), "+f"(d[2]), "+f"(d[3])
                 : "r"(a[0]), "r"(a[1]), "r"(a[2]), "r"(a[3]), "r"(b0), "r"(b1));
}
__device__ __forceinline__ uint32_t cvt2bf(float lo, float hi) {
    uint32_t r;
    asm("cvt.rn.bf16x2.f32 %0, %1, %2;" : "=r"(r) : "f"(hi), "f"(lo));
    return r;
}

// ---------------- zero scratch + dtype detection (merged) ----------------
__global__ void k_zerodetect(const void* eidx, const void* batch) {
    if (blockIdx.x == 0 && threadIdx.x == 0) {
        const unsigned* p = (const unsigned*)eidx;
        int is64 = 1;
        for (int i = 0; i < 32; i++) {
            unsigned lo = p[2 * i], hi = p[2 * i + 1];
            if (hi != 0u || lo >= (unsigned)NHN) { is64 = 0; break; }
        }
        g_is64_e = is64;
        const unsigned* q = (const unsigned*)batch;
        int b64 = 1;
        for (int i = 0; i < 32; i++) {
            unsigned lo = q[2 * i], hi = q[2 * i + 1];
            if (hi != 0u || lo >= (unsigned)NGR) { b64 = 0; break; }
        }
        g_is64_b = b64;
    }
    long long n4 = (long long)NGN * 128 / 4;
    long long stride = (long long)gridDim.x * blockDim.x;
    for (long long i = (long long)blockIdx.x * blockDim.x + threadIdx.x; i < n4; i += stride)
        ((float4*)g_S)[i] = make_float4(0.f, 0.f, 0.f, 0.f);
    for (long long i = (long long)blockIdx.x * blockDim.x + threadIdx.x; i < NGN; i += stride)
        g_deg[i] = 0;
}

// ---------------- weight precompute / transposes ----------------
__global__ void k_prep(const float* __restrict__ W1a, const float* __restrict__ W1b,
                       const float* __restrict__ W2a, const float* __restrict__ W2b,
                       const float* __restrict__ b1b, const float* __restrict__ u) {
    int b = blockIdx.x, t = threadIdx.x;
    if (b < 128) {
        __shared__ float wrow[128];
        wrow[t] = W2a[b * 320 + 128 + t];
        __syncthreads();
        float s = 0.f;
        for (int p = 0; p < 128; p++) s += wrow[p] * W1b[p * 128 + t];
        g_WtN1[(128 + t) * 128 + b] = s;
        if (t == 0) {
            float c = 0.f;
            for (int p = 0; p < 128; p++) c += wrow[p] * b1b[p];
            g_cvec[b] = c;
        }
    } else if (b == 128) {
        // full W1a^T split: WtF[k][j] = W1a[j,k], k,j in [0,128)
        for (int i = t; i < 128 * 128; i += 128) {
            int k = i >> 7, j = i & 127;
            float w = W1a[j * 128 + k];
            __nv_bfloat16 h = __float2bfloat16(w);
            g_WtFh[i] = h;
            g_WtFl[i] = __float2bfloat16(w - __bfloat162float(h));
        }
    } else if (b == 129) {
        for (int i = t; i < 128 * 128; i += 128) {
            int k = i >> 7, j = i & 127;
            g_WtN1[i] = W2a[j * 320 + k];
        }
    } else if (b == 130) {
        for (int i = t; i < 128 * 128; i += 128) {
            int k = i >> 7, j = i & 127;
            g_WtN2[i] = W2b[j * 128 + k];
        }
    } else {
        for (int i = t; i < NGR * 128; i += 128) {
            int g = i >> 7, j = i & 127;
            float s = 0.f;
            for (int k = 0; k < 64; k++) s += u[g * 64 + k] * W2a[j * 320 + 256 + k];
            g_UW[i] = s;
        }
    }
}

// ================= tensor-core edge kernel =================
// z_e[128j] = [x_h[src_e] | EA_e] (K=128) @ W1a^T + b1a ; leaky ; red -> g_S ; deg.
// Two phases: phase 0 stages A cols 0..63 = x_h gather, phase 1 = EA stream.
#define AE_STR 72     // bf16 per A row (64 + 8 pad)
#define BE_STR 136    // bf16 per B row (128 + 8 pad)
#define SME_AL 18432
#define SME_BH 36864
#define SME_BL 54272
#define SME_IDX 71680   // 128 src + 128 tgt ints
#define SME_TOT 72704

__device__ __forceinline__ void split_store(__nv_bfloat16* Ah, __nv_bfloat16* Al,
                                            int off, float4 v) {
    uint32_t ph01 = cvt2bf(v.x, v.y);
    uint32_t ph23 = cvt2bf(v.z, v.w);
    float l0 = v.x - __uint_as_float(ph01 << 16);
    float l1 = v.y - __uint_as_float(ph01 & 0xffff0000u);
    float l2 = v.z - __uint_as_float(ph23 << 16);
    float l3 = v.w - __uint_as_float(ph23 & 0xffff0000u);
    uint32_t pl01 = cvt2bf(l0, l1);
    uint32_t pl23 = cvt2bf(l2, l3);
    *(uint2*)(Ah + off) = make_uint2(ph01, ph23);
    *(uint2*)(Al + off) = make_uint2(pl01, pl23);
}

extern __shared__ __align__(16) char smdyn[];

__launch_bounds__(256, 2)
__global__ void k_edge(const float* __restrict__ EA, const float* __restrict__ XH,
                       const float* __restrict__ b1a, const void* __restrict__ eidx) {
    __nv_bfloat16* Ah = (__nv_bfloat16*)smdyn;
    __nv_bfloat16* Al = (__nv_bfloat16*)(smdyn + SME_AL);
    __nv_bfloat16* Bh = (__nv_bfloat16*)(smdyn + SME_BH);
    __nv_bfloat16* Bl = (__nv_bfloat16*)(smdyn + SME_BL);
    int* src_s = (int*)(smdyn + SME_IDX);
    int* tgt_s = src_s + 128;
    float* Cs = (float*)smdyn;

    const int tid = threadIdx.x;
    const int lane = tid & 31, wid = tid >> 5;
    const int wm = (wid & 3) * 32;
    const int wn = (wid >> 2) * 64;
    const long long m0 = (long long)blockIdx.x * 128;

    // stage edge indices (src, tgt) for this block
    {
        const int is64 = g_is64_e;
        if (tid < 128) {
            long long er = m0 + tid;
            src_s[tid] = is64 ? (int)((const long long*)eidx)[er]
                              : ((const int*)eidx)[er];
        } else {
            long long er = m0 + (tid - 128);
            tgt_s[tid - 128] = is64 ? (int)((const long long*)eidx)[(long long)NE + er]
                                    : ((const int*)eidx)[(long long)NE + er];
        }
    }

    float d[2][8][4];
#pragma unroll
    for (int mf = 0; mf < 2; mf++)
#pragma unroll
        for (int nf = 0; nf < 8; nf++)
#pragma unroll
            for (int e = 0; e < 4; e++) d[mf][nf][e] = 0.f;

    const uint32_t uAh = s2u(Ah), uAl = s2u(Al), uBh = s2u(Bh), uBl = s2u(Bl);

    __syncthreads();   // src_s ready

#pragma unroll
    for (int ph = 0; ph < 2; ph++) {
        // ---- stage A tile [128 x 64]: phase 0 = x_h[src] gather, phase 1 = EA stream ----
#pragma unroll
        for (int it = 0; it < 8; it++) {
            int q = tid + it * 256;
            int m = q >> 4, k4 = q & 15;
            float4 v;
            if (ph == 0) {
                long long row = src_s[m];
                v = ((const float4*)(XH + row * 64))[k4];
            } else {
                v = ((const float4*)(EA + (m0 + m) * 64))[k4];
            }
            split_store(Ah, Al, m * AE_STR + k4 * 4, v);
        }
        // ---- stage B tile: rows [ph*64, ph*64+64) of WtF hi/lo ----
#pragma unroll
        for (int it = 0; it < 8; it++) {
            int q = tid + it * 256;
            int row = q >> 5, c = q & 31;
            int off = row * BE_STR + c * 4;
            *(uint2*)(Bh + off) = *(const uint2*)(g_WtFh + (ph * 64 + row) * 128 + c * 4);
            *(uint2*)(Bl + off) = *(const uint2*)(g_WtFl + (ph * 64 + row) * 128 + c * 4);
        }
        __syncthreads();

        // ---- 4 x k16 mma chunks ----
#pragma unroll
        for (int kc = 0; kc < 4; kc++) {
            uint32_t ah[2][4], al[2][4];
#pragma unroll
            for (int mf = 0; mf < 2; mf++) {
                uint32_t aoff = (uint32_t)(((wm + mf * 16 + (lane & 15)) * AE_STR +
                                            kc * 16 + ((lane >> 4) << 3)) * 2);
                ldm4(ah[mf], uAh + aoff);
                ldm4(al[mf], uAl + aoff);
            }
#pragma unroll
            for (int nf2 = 0; nf2 < 4; nf2++) {
                uint32_t boff = (uint32_t)(((kc * 16 + (lane & 15)) * BE_STR +
                                            wn + nf2 * 16 + ((lane >> 4) << 3)) * 2);
                uint32_t bh[4], bl[4];
                ldm4t(bh, uBh + boff);
                ldm4t(bl, uBl + boff);
#pragma unroll
                for (int mf = 0; mf < 2; mf++) {
#pragma unroll
                    for (int tt = 0; tt < 2; tt++) {
                        float* dd = d[mf][nf2 * 2 + tt];
                        mma16816(dd, ah[mf], bh[2 * tt], bh[2 * tt + 1]);
                        mma16816(dd, ah[mf], bl[2 * tt], bl[2 * tt + 1]);
                        mma16816(dd, al[mf], bh[2 * tt], bh[2 * tt + 1]);
                    }
                }
            }
        }
        __syncthreads();
    }

    // ---- epilogue: leaky(C + b1a) -> red to g_S ; deg count ----
    const int tx = tid & 15, ty = tid >> 4;
    const int c0 = tx * 8;
    float bloc[8];
#pragma unroll
    for (int j = 0; j < 8; j++) bloc[j] = b1a[c0 + j];
#pragma unroll
    for (int p = 0; p < 2; p++) {
        int rowc = (wid & 3) * 16 + (lane >> 2);
        int colc = wn + 2 * (lane & 3);
#pragma unroll
        for (int nf = 0; nf < 8; nf++) {
            *(float2*)&Cs[rowc * 128 + colc + nf * 8] = make_float2(d[p][nf][0], d[p][nf][1]);
            *(float2*)&Cs[(rowc + 8) * 128 + colc + nf * 8] = make_float2(d[p][nf][2], d[p][nf][3]);
        }
        __syncthreads();
#pragma unroll
        for (int rr = 0; rr < 4; rr++) {
            int cs_r = ty * 4 + rr;
            int el = ((cs_r >> 4) << 5) + p * 16 + (cs_r & 15);   // edge index within block
            int t = tgt_s[el];
            const float* cr = Cs + cs_r * 128 + c0;
            float v[8];
#pragma unroll
            for (int j = 0; j < 8; j++) {
                float z = cr[j] + bloc[j];
                v[j] = (z >= 0.f) ? z : 0.1f * z;
            }
            float* dst = g_S + (long long)t * 128 + c0;
            asm volatile("red.global.add.v4.f32 [%0], {%1,%2,%3,%4};"
                         :: "l"(dst), "f"(v[0]), "f"(v[1]), "f"(v[2]), "f"(v[3]) : "memory");
            asm volatile("red.global.add.v4.f32 [%0], {%1,%2,%3,%4};"
                         :: "l"(dst + 4), "f"(v[4]), "f"(v[5]), "f"(v[6]), "f"(v[7]) : "memory");
            if (tx == 0) atomicAdd(&g_deg[t], 1);
        }
        __syncthreads();
    }
}

// ---------------- scalar register-tiled GEMM (modes 2/3) ----------------
template <int KTOT, int MODE>
__launch_bounds__(256)
__global__ void k_gemm(const float* __restrict__ A0, const float* __restrict__ bias,
                       float* __restrict__ Cout, int Mrows, const void* __restrict__ idx) {
    __shared__ float As[128 * 32];
    __shared__ float Bs[32 * 128];

    const int tid = threadIdx.x;
    const int tx = tid & 15, ty = tid >> 4;
    const int r0 = ty * 8, c0 = tx * 8;
    const int m0 = blockIdx.x * 128;

    const float* Bt = (MODE == 2) ? g_WtN1 : g_WtN2;

    unsigned long long acc2[8][4];
#pragma unroll
    for (int i = 0; i < 8; i++)
#pragma unroll
        for (int j = 0; j < 4; j++) acc2[i][j] = 0ull;

    for (int ks = 0; ks < KTOT; ks += 32) {
        const float* Asrc;
        int koff;
        if (MODE == 2) {
            if (ks < 128) { Asrc = A0;  koff = ks; }
            else          { Asrc = g_S; koff = ks - 128; }
        } else {
            Asrc = g_T2; koff = ks;
        }
#pragma unroll
        for (int it = 0; it < 4; it++) {
            int q = tid + it * 256;
            int m = q >> 3, k4 = q & 7;
            float4 v = make_float4(0.f, 0.f, 0.f, 0.f);
            if (m0 + m < Mrows)
                v = ((const float4*)(Asrc + (long long)(m0 + m) * 128 + koff))[k4];
            ((float4*)As)[q] = v;
        }
#pragma unroll
        for (int it = 0; it < 4; it++) {
            int q = tid + it * 256;
            ((float4*)Bs)[q] = ((const float4*)Bt)[(long long)(ks * 32) + q];
        }
        __syncthreads();

#pragma unroll
        for (int kk4 = 0; kk4 < 8; kk4++) {
            float4 av[8];
#pragma unroll
            for (int i = 0; i < 8; i++) av[i] = ((const float4*)As)[(r0 + i) * 8 + kk4];
#pragma unroll
            for (int u = 0; u < 4; u++) {
                const ulonglong2* bp = (const ulonglong2*)(Bs + (kk4 * 4 + u) * 128 + c0);
                ulonglong2 b0 = bp[0];
                ulonglong2 b1 = bp[1];
#pragma unroll
                for (int i = 0; i < 8; i++) {
                    float a = (u == 0) ? av[i].x : (u == 1) ? av[i].y
                             : (u == 2) ? av[i].z : av[i].w;
                    unsigned long long a2 = pack2(a);
                    ffma2(acc2[i][0], a2, b0.x);
                    ffma2(acc2[i][1], a2, b0.y);
                    ffma2(acc2[i][2], a2, b1.x);
                    ffma2(acc2[i][3], a2, b1.y);
                }
            }
        }
        __syncthreads();
    }

    float acc[8][8];
#pragma unroll
    for (int i = 0; i < 8; i++)
#pragma unroll
        for (int j = 0; j < 4; j++) {
            float2 f = unpack2(acc2[i][j]);
            acc[i][2 * j]     = f.x;
            acc[i][2 * j + 1] = f.y;
        }

    if (MODE == 3) {
        float bloc[8];
#pragma unroll
        for (int j = 0; j < 8; j++) bloc[j] = bias[c0 + j];
#pragma unroll
        for (int i = 0; i < 8; i++) {
            int m = m0 + r0 + i;
            if (m < Mrows) {
                float4* dst = (float4*)(Cout + (long long)m * 128 + c0);
                dst[0] = make_float4(acc[i][0] + bloc[0], acc[i][1] + bloc[1],
                                     acc[i][2] + bloc[2], acc[i][3] + bloc[3]);
                dst[1] = make_float4(acc[i][4] + bloc[4], acc[i][5] + bloc[5],
                                     acc[i][6] + bloc[6], acc[i][7] + bloc[7]);
            }
        }
    }
    if (MODE == 2) {
        const int is64 = g_is64_b;
        float bloc[8], cloc[8];
#pragma unroll
        for (int j = 0; j < 8; j++) { bloc[j] = bias[c0 + j]; cloc[j] = g_cvec[c0 + j]; }
#pragma unroll
        for (int i = 0; i < 8; i++) {
            int m = m0 + r0 + i;
            if (m < Mrows) {
                long long g = is64 ? ((const long long*)idx)[m] : (long long)((const int*)idx)[m];
                float dg = (float)g_deg[m];
                const float* uw = g_UW + g * 128 + c0;
                float v[8];
#pragma unroll
                for (int j = 0; j < 8; j++) {
                    float z = acc[i][j] + bloc[j] + dg * cloc[j] + uw[j];
                    v[j] = (z >= 0.f) ? z : 0.1f * z;
                }
                float4* dst = (float4*)(g_T2 + (long long)m * 128 + c0);
                dst[0] = make_float4(v[0], v[1], v[2], v[3]);
                dst[1] = make_float4(v[4], v[5], v[6], v[7]);
            }
        }
    }
}

// ---------------- launch ----------------
extern "C" void kernel_launch(void* const* d_in, const int* in_sizes, int n_in,
                              void* d_out, int out_size) {
    const float* x_h       = (const float*)d_in[0];
    const float* x_g       = (const float*)d_in[1];
    const float* edge_attr = (const float*)d_in[2];
    const float* u         = (const float*)d_in[3];
    const float* W1a       = (const float*)d_in[4];
    const float* b1a       = (const float*)d_in[5];
    const float* W1b       = (const float*)d_in[6];
    const float* b1b       = (const float*)d_in[7];
    const float* W2a       = (const float*)d_in[8];
    const float* b2a       = (const float*)d_in[9];
    const float* W2b       = (const float*)d_in[10];
    const float* b2b       = (const float*)d_in[11];
    const void*  eidx      = d_in[12];
    const void*  batch     = d_in[13];
    float* out = (float*)d_out;

    cudaFuncSetAttribute(k_edge, cudaFuncAttributeMaxDynamicSharedMemorySize, SME_TOT);

    const int gb_nodes = (NGN + 127) / 128;   // 391
    const int gb_edges = NE / 128;            // 12500

    k_zerodetect<<<512, 256>>>(eidx, batch);                             // 0
    k_prep<<<132, 128>>>(W1a, W1b, W2a, W2b, b1b, u);                   // 1
    // edge GEMM K=128 (x_h folded into MMA) + leaky + scatter-red
    k_edge<<<gb_edges, 256, SME_TOT>>>(edge_attr, x_h, b1a, eidx);      // 2
    k_gemm<256, 2><<<gb_nodes, 256>>>(x_g, b2a, nullptr, NGN, batch);   // 3
    k_gemm<128, 3><<<gb_nodes, 256>>>(nullptr, b2b, out, NGN, nullptr); // 4
}

// round 13
// speedup vs baseline: 1.4887x; 1.3798x over previous
#include <cuda_runtime.h>
#include <cuda_bf16.h>
#include <cstdint>

#define NHN 50000
#define NGN 50000
#define NE  1600000
#define NGR 16

// ---------------- scratch (device globals; no allocations) ----------------
__device__ __align__(16) float g_H1[(size_t)NHN * 128];   // x_h@W1aL^T + b1a
__device__ __align__(16) float g_S [(size_t)NGN * 128];   // sum of leaky(z_e) per target
__device__ __align__(16) float g_T2[(size_t)NGN * 128];   // leaky(node-MLP stage1)
__device__ __align__(16) float g_WtH1[64 * 128];          // W1a[:, :64]^T (fp32 staging)
__device__ __align__(16) float g_WtN1[256 * 128];         // staging
__device__ __align__(16) float g_WtN2[128 * 128];         // staging
__device__ __align__(16) __nv_bfloat16 g_WtEh[64 * 128];  // W1a[:,64:]^T hi
__device__ __align__(16) __nv_bfloat16 g_WtEl[64 * 128];  // lo
__device__ __align__(16) __nv_bfloat16 g_WtH1h[64 * 128];
__device__ __align__(16) __nv_bfloat16 g_WtH1l[64 * 128];
__device__ __align__(16) __nv_bfloat16 g_WtN1h[256 * 128];
__device__ __align__(16) __nv_bfloat16 g_WtN1l[256 * 128];
__device__ __align__(16) __nv_bfloat16 g_WtN2h[128 * 128];
__device__ __align__(16) __nv_bfloat16 g_WtN2l[128 * 128];
__device__ __align__(16) float g_cvec[128];
__device__ __align__(16) float g_UW[NGR * 128];
__device__ int g_deg[NGN];
__device__ int g_is64_e;
__device__ int g_is64_b;

// ---------------- mma helpers ----------------
__device__ __forceinline__ uint32_t s2u(const void* p) {
    return (uint32_t)__cvta_generic_to_shared(p);
}
__device__ __forceinline__ void ldm4(uint32_t* r, uint32_t addr) {
    asm volatile("ldmatrix.sync.aligned.m8n8.x4.shared.b16 {%0,%1,%2,%3}, [%4];"
                 : "=r"(r[0]), "=r"(r[1]), "=r"(r[2]), "=r"(r[3]) : "r"(addr));
}
__device__ __forceinline__ void ldm4t(uint32_t* r, uint32_t addr) {
    asm volatile("ldmatrix.sync.aligned.m8n8.x4.trans.shared.b16 {%0,%1,%2,%3}, [%4];"
                 : "=r"(r[0]), "=r"(r[1]), "=r"(r[2]), "=r"(r[3]) : "r"(addr));
}
__device__ __forceinline__ void mma16816(float* d, const uint32_t* a, uint32_t b0, uint32_t b1) {
    asm volatile("mma.sync.aligned.m16n8k16.row.col.f32.bf16.bf16.f32 "
                 "{%0,%1,%2,%3}, {%4,%5,%6,%7}, {%8,%9}, {%0,%1,%2,%3};"
                 : "+f"(d[0]), "+f"(d[1]), "+f"(d[2]), "+f"(d[3])
                 : "r"(a[0]), "r"(a[1]), "r"(a[2]), "r"(a[3]), "r"(b0), "r"(b1));
}
__device__ __forceinline__ uint32_t cvt2bf(float lo, float hi) {
    uint32_t r;
    asm("cvt.rn.bf16x2.f32 %0, %1, %2;" : "=r"(r) : "f"(hi), "f"(lo));
    return r;
}

// ---------------- zero scratch + dtype detection ----------------
__global__ void k_zerodetect(const void* eidx, const void* batch) {
    if (blockIdx.x == 0 && threadIdx.x == 0) {
        const unsigned* p = (const unsigned*)eidx;
        int is64 = 1;
        for (int i = 0; i < 32; i++) {
            unsigned lo = p[2 * i], hi = p[2 * i + 1];
            if (hi != 0u || lo >= (unsigned)NHN) { is64 = 0; break; }
        }
        g_is64_e = is64;
        const unsigned* q = (const unsigned*)batch;
        int b64 = 1;
        for (int i = 0; i < 32; i++) {
            unsigned lo = q[2 * i], hi = q[2 * i + 1];
            if (hi != 0u || lo >= (unsigned)NGR) { b64 = 0; break; }
        }
        g_is64_b = b64;
    }
    long long n4 = (long long)NGN * 128 / 4;
    long long stride = (long long)gridDim.x * blockDim.x;
    for (long long i = (long long)blockIdx.x * blockDim.x + threadIdx.x; i < n4; i += stride)
        ((float4*)g_S)[i] = make_float4(0.f, 0.f, 0.f, 0.f);
    for (long long i = (long long)blockIdx.x * blockDim.x + threadIdx.x; i < NGN; i += stride)
        g_deg[i] = 0;
}

// ---------------- weight precompute / transposes ----------------
__global__ void k_prep(const float* __restrict__ W1a, const float* __restrict__ W1b,
                       const float* __restrict__ W2a, const float* __restrict__ W2b,
                       const float* __restrict__ b1b, const float* __restrict__ u) {
    int b = blockIdx.x, t = threadIdx.x;
    if (b < 128) {
        __shared__ float wrow[128];
        wrow[t] = W2a[b * 320 + 128 + t];
        __syncthreads();
        float s = 0.f;
        for (int p = 0; p < 128; p++) s += wrow[p] * W1b[p * 128 + t];
        g_WtN1[(128 + t) * 128 + b] = s;
        if (t == 0) {
            float c = 0.f;
            for (int p = 0; p < 128; p++) c += wrow[p] * b1b[p];
            g_cvec[b] = c;
        }
    } else if (b == 128) {
        for (int i = t; i < 64 * 128; i += 128) {
            int k = i >> 7, j = i & 127;
            g_WtH1[i] = W1a[j * 128 + k];
            float w = W1a[j * 128 + 64 + k];
            __nv_bfloat16 h = __float2bfloat16(w);
            g_WtEh[i] = h;
            g_WtEl[i] = __float2bfloat16(w - __bfloat162float(h));
        }
    } else if (b == 129) {
        for (int i = t; i < 128 * 128; i += 128) {
            int k = i >> 7, j = i & 127;
            g_WtN1[i] = W2a[j * 320 + k];
        }
    } else if (b == 130) {
        for (int i = t; i < 128 * 128; i += 128) {
            int k = i >> 7, j = i & 127;
            g_WtN2[i] = W2b[j * 128 + k];
        }
    } else {
        for (int i = t; i < NGR * 128; i += 128) {
            int g = i >> 7, j = i & 127;
            float s = 0.f;
            for (int k = 0; k < 64; k++) s += u[g * 64 + k] * W2a[j * 320 + 256 + k];
            g_UW[i] = s;
        }
    }
}

// split staged fp32 weights into bf16 hi/lo (after k_prep)
__global__ void k_split() {
    int i = blockIdx.x * blockDim.x + threadIdx.x;
    if (i < 8192) {
        float w = g_WtH1[i];
        __nv_bfloat16 h = __float2bfloat16(w);
        g_WtH1h[i] = h;
        g_WtH1l[i] = __float2bfloat16(w - __bfloat162float(h));
    } else if (i < 8192 + 32768) {
        int j = i - 8192;
        float w = g_WtN1[j];
        __nv_bfloat16 h = __float2bfloat16(w);
        g_WtN1h[j] = h;
        g_WtN1l[j] = __float2bfloat16(w - __bfloat162float(h));
    } else if (i < 8192 + 32768 + 16384) {
        int j = i - 8192 - 32768;
        float w = g_WtN2[j];
        __nv_bfloat16 h = __float2bfloat16(w);
        g_WtN2h[j] = h;
        g_WtN2l[j] = __float2bfloat16(w - __bfloat162float(h));
    }
}

// ---------------- shared split-store helper ----------------
__device__ __forceinline__ void split_store(__nv_bfloat16* Ah, __nv_bfloat16* Al,
                                            int off, float4 v) {
    uint32_t ph01 = cvt2bf(v.x, v.y);
    uint32_t ph23 = cvt2bf(v.z, v.w);
    float l0 = v.x - __uint_as_float(ph01 << 16);
    float l1 = v.y - __uint_as_float(ph01 & 0xffff0000u);
    float l2 = v.z - __uint_as_float(ph23 << 16);
    float l3 = v.w - __uint_as_float(ph23 & 0xffff0000u);
    uint32_t pl01 = cvt2bf(l0, l1);
    uint32_t pl23 = cvt2bf(l2, l3);
    *(uint2*)(Ah + off) = make_uint2(ph01, ph23);
    *(uint2*)(Al + off) = make_uint2(pl01, pl23);
}

// ================= tensor-core edge kernel (R6 exact: two-phase, K=64) =================
#define A_STR 40
#define B_STR 136
#define SM_AL 10240
#define SM_BH 20480
#define SM_BL 29184
#define SM_TOT 37888

__launch_bounds__(256, 2)
__global__ void k_edge(const float* __restrict__ EA, const void* __restrict__ eidx) {
    __shared__ __align__(16) char sm[SM_TOT];
    __nv_bfloat16* Ah = (__nv_bfloat16*)sm;
    __nv_bfloat16* Al = (__nv_bfloat16*)(sm + SM_AL);
    __nv_bfloat16* Bh = (__nv_bfloat16*)(sm + SM_BH);
    __nv_bfloat16* Bl = (__nv_bfloat16*)(sm + SM_BL);
    float* Cs = (float*)sm;

    const int tid = threadIdx.x;
    const int lane = tid & 31, wid = tid >> 5;
    const int wm = (wid & 3) * 32;
    const int wn = (wid >> 2) * 64;
    const long long m0 = (long long)blockIdx.x * 128;

    float d[2][8][4];
#pragma unroll
    for (int mf = 0; mf < 2; mf++)
#pragma unroll
        for (int nf = 0; nf < 8; nf++)
#pragma unroll
            for (int e = 0; e < 4; e++) d[mf][nf][e] = 0.f;

    const uint32_t uAh = s2u(Ah), uAl = s2u(Al), uBh = s2u(Bh), uBl = s2u(Bl);

    for (int ks = 0; ks < 64; ks += 32) {
#pragma unroll
        for (int it = 0; it < 4; it++) {
            int q = tid + it * 256;
            int m = q >> 3, k4 = q & 7;
            float4 v = ((const float4*)(EA + (m0 + m) * 64 + ks))[k4];
            split_store(Ah, Al, m * A_STR + k4 * 4, v);
        }
#pragma unroll
        for (int it = 0; it < 4; it++) {
            int q = tid + it * 256;
            int row = q >> 5, c = q & 31;
            int off = row * B_STR + c * 4;
            *(uint2*)(Bh + off) = *(const uint2*)(g_WtEh + (ks + row) * 128 + c * 4);
            *(uint2*)(Bl + off) = *(const uint2*)(g_WtEl + (ks + row) * 128 + c * 4);
        }
        __syncthreads();

#pragma unroll
        for (int kc = 0; kc < 2; kc++) {
            uint32_t ah[2][4], al[2][4];
#pragma unroll
            for (int mf = 0; mf < 2; mf++) {
                uint32_t aoff = (uint32_t)(((wm + mf * 16 + (lane & 15)) * A_STR +
                                            kc * 16 + ((lane >> 4) << 3)) * 2);
                ldm4(ah[mf], uAh + aoff);
                ldm4(al[mf], uAl + aoff);
            }
#pragma unroll
            for (int nf2 = 0; nf2 < 4; nf2++) {
                uint32_t boff = (uint32_t)(((kc * 16 + (lane & 15)) * B_STR +
                                            wn + nf2 * 16 + ((lane >> 4) << 3)) * 2);
                uint32_t bh[4], bl[4];
                ldm4t(bh, uBh + boff);
                ldm4t(bl, uBl + boff);
#pragma unroll
                for (int mf = 0; mf < 2; mf++) {
#pragma unroll
                    for (int tt = 0; tt < 2; tt++) {
                        float* dd = d[mf][nf2 * 2 + tt];
                        mma16816(dd, ah[mf], bh[2 * tt], bh[2 * tt + 1]);
                        mma16816(dd, ah[mf], bl[2 * tt], bl[2 * tt + 1]);
                        mma16816(dd, al[mf], bh[2 * tt], bh[2 * tt + 1]);
                    }
                }
            }
        }
        __syncthreads();
    }

    const int is64 = g_is64_e;
    const int tx = tid & 15, ty = tid >> 4;
    const int c0 = tx * 8;
#pragma unroll
    for (int p = 0; p < 2; p++) {
        int rowc = (wid & 3) * 16 + (lane >> 2);
        int colc = wn + 2 * (lane & 3);
#pragma unroll
        for (int nf = 0; nf < 8; nf++) {
            *(float2*)&Cs[rowc * 128 + colc + nf * 8] = make_float2(d[p][nf][0], d[p][nf][1]);
            *(float2*)&Cs[(rowc + 8) * 128 + colc + nf * 8] = make_float2(d[p][nf][2], d[p][nf][3]);
        }
        __syncthreads();
#pragma unroll
        for (int rr = 0; rr < 4; rr++) {
            int cs_r = ty * 4 + rr;
            long long er = m0 + ((cs_r >> 4) << 5) + p * 16 + (cs_r & 15);
            long long s, t;
            if (is64) {
                s = ((const long long*)eidx)[er];
                t = ((const long long*)eidx)[(long long)NE + er];
            } else {
                s = ((const int*)eidx)[er];
                t = ((const int*)eidx)[(long long)NE + er];
            }
            const float4* h = (const float4*)(g_H1 + s * 128 + c0);
            float4 h0 = h[0], h1 = h[1];
            const float* cr = Cs + cs_r * 128 + c0;
            float v[8];
            v[0] = cr[0] + h0.x; v[1] = cr[1] + h0.y; v[2] = cr[2] + h0.z; v[3] = cr[3] + h0.w;
            v[4] = cr[4] + h1.x; v[5] = cr[5] + h1.y; v[6] = cr[6] + h1.z; v[7] = cr[7] + h1.w;
#pragma unroll
            for (int j = 0; j < 8; j++) v[j] = (v[j] >= 0.f) ? v[j] : 0.1f * v[j];
            float* dst = g_S + t * 128 + c0;
            asm volatile("red.global.add.v4.f32 [%0], {%1,%2,%3,%4};"
                         :: "l"(dst), "f"(v[0]), "f"(v[1]), "f"(v[2]), "f"(v[3]) : "memory");
            asm volatile("red.global.add.v4.f32 [%0], {%1,%2,%3,%4};"
                         :: "l"(dst + 4), "f"(v[4]), "f"(v[5]), "f"(v[6]), "f"(v[7]) : "memory");
            if (tx == 0) atomicAdd(&g_deg[(int)t], 1);
        }
        __syncthreads();
    }
}

// ================= tensor-core node GEMM: 64x128 block tile =================
// MODE 0: H1 = x_h @ WtH1 + b1a                (K=64,  lda=64)
// MODE 2: T2 = leaky([x_g|g_S]@WtN1 + b2a + deg*cvec + UW[batch])  (K=256)
// MODE 3: out = g_T2 @ WtN2 + b2b              (K=128)
#define AN_STR 40
#define BN_STR 136
#define NSM_AL 5120
#define NSM_BH 10240
#define NSM_BL 18944
#define NSM_TOT 32768   // Cs (64x128 f32) overlays everything

template <int KTOT, int MODE>
__launch_bounds__(256, 2)
__global__ void k_tg(const float* __restrict__ A0, const float* __restrict__ bias,
                     float* __restrict__ Cout, int Mrows, const void* __restrict__ idx) {
    __shared__ __align__(16) char sm[NSM_TOT];
    __nv_bfloat16* Ah = (__nv_bfloat16*)sm;
    __nv_bfloat16* Al = (__nv_bfloat16*)(sm + NSM_AL);
    __nv_bfloat16* Bh = (__nv_bfloat16*)(sm + NSM_BH);
    __nv_bfloat16* Bl = (__nv_bfloat16*)(sm + NSM_BL);
    float* Cs = (float*)sm;

    const int tid = threadIdx.x;
    const int lane = tid & 31, wid = tid >> 5;
    const int wm = (wid & 3) * 16;       // 4 warps in M (64 rows)
    const int wn = (wid >> 2) * 64;      // 2 warps in N (128 cols)
    const int m0 = blockIdx.x * 64;

    const __nv_bfloat16* Wh = (MODE == 0) ? g_WtH1h : (MODE == 2) ? g_WtN1h : g_WtN2h;
    const __nv_bfloat16* Wl = (MODE == 0) ? g_WtH1l : (MODE == 2) ? g_WtN1l : g_WtN2l;

    float d[8][4];
#pragma unroll
    for (int nf = 0; nf < 8; nf++)
#pragma unroll
        for (int e = 0; e < 4; e++) d[nf][e] = 0.f;

    const uint32_t uAh = s2u(Ah), uAl = s2u(Al), uBh = s2u(Bh), uBl = s2u(Bl);

    for (int ks = 0; ks < KTOT; ks += 32) {
        const float* Asrc;
        int koff, lda;
        if (MODE == 2) {
            lda = 128;
            if (ks < 128) { Asrc = A0;  koff = ks; }
            else          { Asrc = g_S; koff = ks - 128; }
        } else if (MODE == 3) {
            Asrc = g_T2; lda = 128; koff = ks;
        } else {
            Asrc = A0; lda = 64; koff = ks;
        }
        // A tile [64 x 32] = 512 float4
#pragma unroll
        for (int it = 0; it < 2; it++) {
            int q = tid + it * 256;
            int m = q >> 3, k4 = q & 7;
            float4 v = make_float4(0.f, 0.f, 0.f, 0.f);
            if (m0 + m < Mrows)
                v = ((const float4*)(Asrc + (long long)(m0 + m) * lda + koff))[k4];
            split_store(Ah, Al, m * AN_STR + k4 * 4, v);
        }
        // B tile rows [ks..ks+32) hi/lo
#pragma unroll
        for (int it = 0; it < 4; it++) {
            int q = tid + it * 256;
            int row = q >> 5, c = q & 31;
            int off = row * BN_STR + c * 4;
            *(uint2*)(Bh + off) = *(const uint2*)(Wh + (ks + row) * 128 + c * 4);
            *(uint2*)(Bl + off) = *(const uint2*)(Wl + (ks + row) * 128 + c * 4);
        }
        __syncthreads();

#pragma unroll
        for (int kc = 0; kc < 2; kc++) {
            uint32_t ah[4], al[4];
            uint32_t aoff = (uint32_t)(((wm + (lane & 15)) * AN_STR +
                                        kc * 16 + ((lane >> 4) << 3)) * 2);
            ldm4(ah, uAh + aoff);
            ldm4(al, uAl + aoff);
#pragma unroll
            for (int nf2 = 0; nf2 < 4; nf2++) {
                uint32_t boff = (uint32_t)(((kc * 16 + (lane & 15)) * BN_STR +
                                            wn + nf2 * 16 + ((lane >> 4) << 3)) * 2);
                uint32_t bh[4], bl[4];
                ldm4t(bh, uBh + boff);
                ldm4t(bl, uBl + boff);
#pragma unroll
                for (int tt = 0; tt < 2; tt++) {
                    float* dd = d[nf2 * 2 + tt];
                    mma16816(dd, ah, bh[2 * tt], bh[2 * tt + 1]);
                    mma16816(dd, ah, bl[2 * tt], bl[2 * tt + 1]);
                    mma16816(dd, al, bh[2 * tt], bh[2 * tt + 1]);
                }
            }
        }
        __syncthreads();
    }

    // stage C to smem
    {
        int rowc = (wid & 3) * 16 + (lane >> 2);
        int colc = wn + 2 * (lane & 3);
#pragma unroll
        for (int nf = 0; nf < 8; nf++) {
            *(float2*)&Cs[rowc * 128 + colc + nf * 8] = make_float2(d[nf][0], d[nf][1]);
            *(float2*)&Cs[(rowc + 8) * 128 + colc + nf * 8] = make_float2(d[nf][2], d[nf][3]);
        }
    }
    __syncthreads();

    // consume: each thread 4 rows x 8 cols
    const int tx = tid & 15, ty = tid >> 4;
    const int c0 = tx * 8;
    float bloc[8];
#pragma unroll
    for (int j = 0; j < 8; j++) bloc[j] = bias[c0 + j];
    const int is64 = g_is64_b;
#pragma unroll
    for (int rr = 0; rr < 4; rr++) {
        int cs_r = ty * 4 + rr;
        int m = m0 + cs_r;
        if (m < Mrows) {
            const float* cr = Cs + cs_r * 128 + c0;
            float v[8];
            if (MODE == 2) {
                long long g = is64 ? ((const long long*)idx)[m]
                                   : (long long)((const int*)idx)[m];
                float dg = (float)g_deg[m];
                const float* uw = g_UW + g * 128 + c0;
#pragma unroll
                for (int j = 0; j < 8; j++) {
                    float z = cr[j] + bloc[j] + dg * g_cvec[c0 + j] + uw[j];
                    v[j] = (z >= 0.f) ? z : 0.1f * z;
                }
            } else {
#pragma unroll
                for (int j = 0; j < 8; j++) v[j] = cr[j] + bloc[j];
            }
            float* C = (MODE == 0) ? g_H1 : (MODE == 2) ? g_T2 : Cout;
            float4* dst = (float4*)(C + (long long)m * 128 + c0);
            dst[0] = make_float4(v[0], v[1], v[2], v[3]);
            dst[1] = make_float4(v[4], v[5], v[6], v[7]);
        }
    }
}

// ---------------- launch ----------------
extern "C" void kernel_launch(void* const* d_in, const int* in_sizes, int n_in,
                              void* d_out, int out_size) {
    const float* x_h       = (const float*)d_in[0];
    const float* x_g       = (const float*)d_in[1];
    const float* edge_attr = (const float*)d_in[2];
    const float* u         = (const float*)d_in[3];
    const float* W1a       = (const float*)d_in[4];
    const float* b1a       = (const float*)d_in[5];
    const float* W1b       = (const float*)d_in[6];
    const float* b1b       = (const float*)d_in[7];
    const float* W2a       = (const float*)d_in[8];
    const float* b2a       = (const float*)d_in[9];
    const float* W2b       = (const float*)d_in[10];
    const float* b2b       = (const float*)d_in[11];
    const void*  eidx      = d_in[12];
    const void*  batch     = d_in[13];
    float* out = (float*)d_out;

    const int gb_n64 = (NGN + 63) / 64;      // 782
    const int gb_edges = NE / 128;           // 12500

    k_zerodetect<<<512, 256>>>(eidx, batch);                              // 0
    k_prep<<<132, 128>>>(W1a, W1b, W2a, W2b, b1b, u);                    // 1
    k_split<<<(57344 + 255) / 256, 256>>>();                              // 2
    k_tg<64, 0><<<gb_n64, 256>>>(x_h, b1a, nullptr, NHN, nullptr);       // 3 <- profiled
    k_edge<<<gb_edges, 256>>>(edge_attr, eidx);                           // 4
    k_tg<256, 2><<<gb_n64, 256>>>(x_g, b2a, nullptr, NGN, batch);        // 5
    k_tg<128, 3><<<gb_n64, 256>>>(nullptr, b2b, out, NGN, nullptr);      // 6
}